// round 1
// baseline (speedup 1.0000x reference)
#include <cuda_runtime.h>
#include <cuda_bf16.h>
#include <cstdint>

// Problem constants
#define BB 1024      // batch
#define UU 8         // units
#define II 512       // input dim
#define HH 512       // hidden dim
#define GN 1536      // 3*H gate dim

// Scratch for the two GEMM results (allowed: __device__ globals, no cudaMalloc)
__device__ float g_gx[(size_t)BB * UU * GN];  // 50 MB
__device__ float g_gh[(size_t)BB * UU * GN];  // 50 MB

// ---------------------------------------------------------------------------
// Tiled NT GEMM: C[b, u, g] = sum_k A[b, u, k] * W[u, g, k] + bias[u, g]
// A is [B, U, K] (row stride U*K due to unit interleave), W is [U, GN, K].
// Block tile 64(M) x 64(N), K-tile 32, 256 threads, 4x4 micro-tile per thread.
// grid: (GN/64, B/64, U*2); z selects (unit, which-matrix).
// ---------------------------------------------------------------------------
__global__ __launch_bounds__(256) void gemm_nt_kernel(
    const float* __restrict__ X,    // inputs  [B,U,I]
    const float* __restrict__ Hi,   // hidden  [B,U,H]
    const float* __restrict__ Wih,  // [U,GN,I]
    const float* __restrict__ Whh,  // [U,GN,H]
    const float* __restrict__ bih,  // [U,GN]
    const float* __restrict__ bhh)  // [U,GN]
{
    const int z = blockIdx.z;
    const int u = z >> 1;
    const int w = z & 1;

    const float* __restrict__ A    = (w == 0) ? X   : Hi;
    const float* __restrict__ Wt   = ((w == 0) ? Wih : Whh) + (size_t)u * GN * II;
    const float* __restrict__ bias = ((w == 0) ? bih : bhh) + (size_t)u * GN;
    float* __restrict__ C          = (w == 0) ? g_gx : g_gh;

    const int m0 = blockIdx.y * 64;  // batch rows
    const int n0 = blockIdx.x * 64;  // gate cols

    // Padded shared tiles: pad=65 makes the transposed stores conflict-free
    // (65 mod 32 == 1 -> bank = k + row spans all banks within a warp).
    __shared__ float As[32][65];
    __shared__ float Bs[32][65];

    const int tid = threadIdx.x;
    const int tx = tid & 15;         // 0..15 -> N micro position
    const int ty = tid >> 4;         // 0..15 -> M micro position

    // loader mapping: each thread loads 2x float4 per tile per matrix
    const int lrow = tid >> 3;        // 0..31
    const int lk   = (tid & 7) * 4;   // 0,4,...,28

    float acc[4][4];
    #pragma unroll
    for (int m = 0; m < 4; ++m)
        #pragma unroll
        for (int n = 0; n < 4; ++n) acc[m][n] = 0.0f;

    for (int k0 = 0; k0 < II; k0 += 32) {
        // A tile: 64 rows (batch) x 32 k, stored k-major (transposed)
        #pragma unroll
        for (int h = 0; h < 2; ++h) {
            const int row = lrow + h * 32;
            const float4 v = *reinterpret_cast<const float4*>(
                &A[((size_t)(m0 + row) * UU + u) * II + k0 + lk]);
            As[lk + 0][row] = v.x;
            As[lk + 1][row] = v.y;
            As[lk + 2][row] = v.z;
            As[lk + 3][row] = v.w;
        }
        // W tile: 64 rows (gates) x 32 k, stored k-major (transposed)
        #pragma unroll
        for (int h = 0; h < 2; ++h) {
            const int row = lrow + h * 32;
            const float4 v = *reinterpret_cast<const float4*>(
                &Wt[(size_t)(n0 + row) * II + k0 + lk]);
            Bs[lk + 0][row] = v.x;
            Bs[lk + 1][row] = v.y;
            Bs[lk + 2][row] = v.z;
            Bs[lk + 3][row] = v.w;
        }
        __syncthreads();

        #pragma unroll
        for (int kk = 0; kk < 32; ++kk) {
            float a[4], b[4];
            #pragma unroll
            for (int m = 0; m < 4; ++m) a[m] = As[kk][ty * 4 + m];
            #pragma unroll
            for (int n = 0; n < 4; ++n) b[n] = Bs[kk][tx * 4 + n];
            #pragma unroll
            for (int m = 0; m < 4; ++m)
                #pragma unroll
                for (int n = 0; n < 4; ++n) acc[m][n] = fmaf(a[m], b[n], acc[m][n]);
        }
        __syncthreads();
    }

    // Epilogue: add bias, write to scratch [B, U, GN]
    #pragma unroll
    for (int m = 0; m < 4; ++m) {
        const int b = m0 + ty * 4 + m;
        #pragma unroll
        for (int n = 0; n < 4; ++n) {
            const int g = n0 + tx * 4 + n;
            C[((size_t)b * UU + u) * GN + g] = acc[m][n] + bias[g];
        }
    }
}

// ---------------------------------------------------------------------------
// Elementwise GRU gate fusion:
//   r = sigmoid(xr+hr); z = sigmoid(xz+hz); n = tanh(xn + r*hn)
//   out = (1-z)*n + z*h
// ---------------------------------------------------------------------------
__global__ __launch_bounds__(256) void gru_elem_kernel(
    const float* __restrict__ Hi,   // hidden [B,U,H]
    float* __restrict__ out)        // [B,U,H]
{
    const int idx = blockIdx.x * blockDim.x + threadIdx.x;  // over B*U*H
    if (idx >= BB * UU * HH) return;

    const int j  = idx & (HH - 1);   // H = 512 (power of 2)
    const int bu = idx >> 9;         // b*U + u

    const float* __restrict__ gx = g_gx + (size_t)bu * GN;
    const float* __restrict__ gh = g_gh + (size_t)bu * GN;

    const float xr = gx[j];
    const float xz = gx[HH + j];
    const float xn = gx[2 * HH + j];
    const float hr = gh[j];
    const float hz = gh[HH + j];
    const float hn = gh[2 * HH + j];

    const float r = 1.0f / (1.0f + __expf(-(xr + hr)));
    const float z = 1.0f / (1.0f + __expf(-(xz + hz)));
    const float n = tanhf(xn + r * hn);
    const float h = Hi[idx];

    out[idx] = (1.0f - z) * n + z * h;
}

extern "C" void kernel_launch(void* const* d_in, const int* in_sizes, int n_in,
                              void* d_out, int out_size)
{
    const float* inputs = (const float*)d_in[0];  // [B,U,I]
    const float* hidden = (const float*)d_in[1];  // [B,U,H]
    const float* W_ih   = (const float*)d_in[2];  // [U,3H,I]
    const float* W_hh   = (const float*)d_in[3];  // [U,3H,H]
    const float* b_ih   = (const float*)d_in[4];  // [U,3H]
    const float* b_hh   = (const float*)d_in[5];  // [U,3H]
    float* out = (float*)d_out;                   // [B,U,H]

    // 16 GEMMs: grid.z = u*2 + which
    dim3 gemm_grid(GN / 64, BB / 64, UU * 2);     // (24, 16, 16)
    gemm_nt_kernel<<<gemm_grid, 256>>>(inputs, hidden, W_ih, W_hh, b_ih, b_hh);

    const int total = BB * UU * HH;               // 4,194,304
    gru_elem_kernel<<<total / 256, 256>>>(hidden, out);
}

// round 2
// speedup vs baseline: 1.0002x; 1.0002x over previous
#include <cuda_runtime.h>
#include <cuda_bf16.h>
#include <cstdint>

// Problem constants
#define BB 1024      // batch
#define UU 8         // units
#define II 512       // input dim
#define HH 512       // hidden dim
#define GN 1536      // 3*H gate dim

// Scratch for the two GEMM results (allowed: __device__ globals, no cudaMalloc)
__device__ float g_gx[(size_t)BB * UU * GN];  // 50 MB
__device__ float g_gh[(size_t)BB * UU * GN];  // 50 MB

// ---------------------------------------------------------------------------
// Tiled NT GEMM: C[b, u, g] = sum_k A[b, u, k] * W[u, g, k] + bias[u, g]
// A is [B, U, K] (row stride U*K due to unit interleave), W is [U, GN, K].
// Block tile 64(M) x 64(N), K-tile 32, 256 threads, 4x4 micro-tile per thread.
// grid: (GN/64, B/64, U*2); z selects (unit, which-matrix).
// ---------------------------------------------------------------------------
__global__ __launch_bounds__(256) void gemm_nt_kernel(
    const float* __restrict__ X,    // inputs  [B,U,I]
    const float* __restrict__ Hi,   // hidden  [B,U,H]
    const float* __restrict__ Wih,  // [U,GN,I]
    const float* __restrict__ Whh,  // [U,GN,H]
    const float* __restrict__ bih,  // [U,GN]
    const float* __restrict__ bhh)  // [U,GN]
{
    const int z = blockIdx.z;
    const int u = z >> 1;
    const int w = z & 1;

    const float* __restrict__ A    = (w == 0) ? X   : Hi;
    const float* __restrict__ Wt   = ((w == 0) ? Wih : Whh) + (size_t)u * GN * II;
    const float* __restrict__ bias = ((w == 0) ? bih : bhh) + (size_t)u * GN;
    float* __restrict__ C          = (w == 0) ? g_gx : g_gh;

    const int m0 = blockIdx.y * 64;  // batch rows
    const int n0 = blockIdx.x * 64;  // gate cols

    // Padded shared tiles: pad=65 makes the transposed stores conflict-free
    // (65 mod 32 == 1 -> bank = k + row spans all banks within a warp).
    __shared__ float As[32][65];
    __shared__ float Bs[32][65];

    const int tid = threadIdx.x;
    const int tx = tid & 15;         // 0..15 -> N micro position
    const int ty = tid >> 4;         // 0..15 -> M micro position

    // loader mapping: each thread loads 2x float4 per tile per matrix
    const int lrow = tid >> 3;        // 0..31
    const int lk   = (tid & 7) * 4;   // 0,4,...,28

    float acc[4][4];
    #pragma unroll
    for (int m = 0; m < 4; ++m)
        #pragma unroll
        for (int n = 0; n < 4; ++n) acc[m][n] = 0.0f;

    for (int k0 = 0; k0 < II; k0 += 32) {
        // A tile: 64 rows (batch) x 32 k, stored k-major (transposed)
        #pragma unroll
        for (int h = 0; h < 2; ++h) {
            const int row = lrow + h * 32;
            const float4 v = *reinterpret_cast<const float4*>(
                &A[((size_t)(m0 + row) * UU + u) * II + k0 + lk]);
            As[lk + 0][row] = v.x;
            As[lk + 1][row] = v.y;
            As[lk + 2][row] = v.z;
            As[lk + 3][row] = v.w;
        }
        // W tile: 64 rows (gates) x 32 k, stored k-major (transposed)
        #pragma unroll
        for (int h = 0; h < 2; ++h) {
            const int row = lrow + h * 32;
            const float4 v = *reinterpret_cast<const float4*>(
                &Wt[(size_t)(n0 + row) * II + k0 + lk]);
            Bs[lk + 0][row] = v.x;
            Bs[lk + 1][row] = v.y;
            Bs[lk + 2][row] = v.z;
            Bs[lk + 3][row] = v.w;
        }
        __syncthreads();

        #pragma unroll
        for (int kk = 0; kk < 32; ++kk) {
            float a[4], b[4];
            #pragma unroll
            for (int m = 0; m < 4; ++m) a[m] = As[kk][ty * 4 + m];
            #pragma unroll
            for (int n = 0; n < 4; ++n) b[n] = Bs[kk][tx * 4 + n];
            #pragma unroll
            for (int m = 0; m < 4; ++m)
                #pragma unroll
                for (int n = 0; n < 4; ++n) acc[m][n] = fmaf(a[m], b[n], acc[m][n]);
        }
        __syncthreads();
    }

    // Epilogue: add bias, write to scratch [B, U, GN]
    #pragma unroll
    for (int m = 0; m < 4; ++m) {
        const int b = m0 + ty * 4 + m;
        #pragma unroll
        for (int n = 0; n < 4; ++n) {
            const int g = n0 + tx * 4 + n;
            C[((size_t)b * UU + u) * GN + g] = acc[m][n] + bias[g];
        }
    }
}

// ---------------------------------------------------------------------------
// Elementwise GRU gate fusion:
//   r = sigmoid(xr+hr); z = sigmoid(xz+hz); n = tanh(xn + r*hn)
//   out = (1-z)*n + z*h
// ---------------------------------------------------------------------------
__global__ __launch_bounds__(256) void gru_elem_kernel(
    const float* __restrict__ Hi,   // hidden [B,U,H]
    float* __restrict__ out)        // [B,U,H]
{
    const int idx = blockIdx.x * blockDim.x + threadIdx.x;  // over B*U*H
    if (idx >= BB * UU * HH) return;

    const int j  = idx & (HH - 1);   // H = 512 (power of 2)
    const int bu = idx >> 9;         // b*U + u

    const float* __restrict__ gx = g_gx + (size_t)bu * GN;
    const float* __restrict__ gh = g_gh + (size_t)bu * GN;

    const float xr = gx[j];
    const float xz = gx[HH + j];
    const float xn = gx[2 * HH + j];
    const float hr = gh[j];
    const float hz = gh[HH + j];
    const float hn = gh[2 * HH + j];

    const float r = 1.0f / (1.0f + __expf(-(xr + hr)));
    const float z = 1.0f / (1.0f + __expf(-(xz + hz)));
    const float n = tanhf(xn + r * hn);
    const float h = Hi[idx];

    out[idx] = (1.0f - z) * n + z * h;
}

extern "C" void kernel_launch(void* const* d_in, const int* in_sizes, int n_in,
                              void* d_out, int out_size)
{
    const float* inputs = (const float*)d_in[0];  // [B,U,I]
    const float* hidden = (const float*)d_in[1];  // [B,U,H]
    const float* W_ih   = (const float*)d_in[2];  // [U,3H,I]
    const float* W_hh   = (const float*)d_in[3];  // [U,3H,H]
    const float* b_ih   = (const float*)d_in[4];  // [U,3H]
    const float* b_hh   = (const float*)d_in[5];  // [U,3H]
    float* out = (float*)d_out;                   // [B,U,H]

    // 16 GEMMs: grid.z = u*2 + which
    dim3 gemm_grid(GN / 64, BB / 64, UU * 2);     // (24, 16, 16)
    gemm_nt_kernel<<<gemm_grid, 256>>>(inputs, hidden, W_ih, W_hh, b_ih, b_hh);

    const int total = BB * UU * HH;               // 4,194,304
    gru_elem_kernel<<<total / 256, 256>>>(hidden, out);
}